// round 15
// baseline (speedup 1.0000x reference)
#include <cuda_runtime.h>

typedef unsigned long long ull;

#define NSEQ 2048
#define NRES 512
#define CIN  64
#define NH   8
#define NC   8

// ---------------- scratch (device globals: allocation-free) ----------------
__device__ __align__(16) float g_k[(size_t)NRES * NSEQ * NC];      // 32 MB
__device__ __align__(16) float g_v[(size_t)NRES * NSEQ * NC];      // 32 MB
__device__ __align__(16) float g_xt[(size_t)NRES * CIN * NSEQ];    // 256 MB  X^T [r][k][n]
__device__ __align__(16) float g_maskT[(size_t)NRES * NSEQ];       // 4 MB    mask^T [r][n]
__device__ __align__(16) float g_qpart[NRES * 16 * CIN];
__device__ __align__(16) float g_mpart[NRES * 16];
__device__ __align__(16) float g_o[NRES * CIN];

// ---------------- packed f32x2 helpers ----------------
__device__ __forceinline__ ull fma2(ull a, ull b, ull c) {
    ull d;
    asm("fma.rn.f32x2 %0, %1, %2, %3;" : "=l"(d) : "l"(a), "l"(b), "l"(c));
    return d;
}
__device__ __forceinline__ ull dup2(float x) {
    ull d; unsigned xi = __float_as_uint(x);
    asm("mov.b64 %0, {%1, %1};" : "=l"(d) : "r"(xi));
    return d;
}
__device__ __forceinline__ ull pack2(float lo, float hi) {
    ull d;
    asm("mov.b64 %0, {%1, %2};" : "=l"(d) : "r"(__float_as_uint(lo)), "r"(__float_as_uint(hi)));
    return d;
}
__device__ __forceinline__ float2 unpk(ull a) {
    unsigned lo, hi;
    asm("mov.b64 {%0, %1}, %2;" : "=r"(lo), "=r"(hi) : "l"(a));
    return make_float2(__uint_as_float(lo), __uint_as_float(hi));
}
__device__ __forceinline__ float wsum(float v) {
#pragma unroll
    for (int o = 16; o; o >>= 1) v += __shfl_xor_sync(0xffffffffu, v, o);
    return v;
}

// buf row swizzle: channel group (k>>4) XORs the row by 0/8/16/24.
__device__ __forceinline__ int bswz(int k) { return ((k >> 4) & 3) << 3; }

// =====================================================================
// Pass 1 (R12 exact): block = (r, 128 n-rows), 4 CTAs/SM.
// =====================================================================
#define P1_SMEM_FLOATS (8192 + 4352 + 1088 + 128 + 512 + 8)
#define P1_SMEM_BYTES  (P1_SMEM_FLOATS * 4)

__global__ void __launch_bounds__(256, 4) pass1_kernel(
    const float* __restrict__ m, const float* __restrict__ mask,
    const float* __restrict__ lnw, const float* __restrict__ lnb,
    const float* __restrict__ wk, const float* __restrict__ wv)
{
    extern __shared__ __align__(16) float sm1[];
    float* buf    = sm1;                    // 8192: X[k][row ^ bswz(k)]
    float* raw    = sm1 + 8192;             // 4352: m half-tile [row][68]
    float* kv_s   = sm1 + 8192;             // 2048: kv staging (aliases raw)
    float* wkv_t  = sm1 + 12544;            // 1088
    float* lnw_s  = sm1 + 13632;
    float* lnb_s  = sm1 + 13696;
    float* qred   = sm1 + 13760;
    float* mred   = sm1 + 14272;

    const int r   = blockIdx.x;
    const int by  = blockIdx.y;
    const int n0  = by * 128;
    const int tid = threadIdx.x;
    const int lane = tid & 31, warp = tid >> 5;
    const int slot = tid >> 2, quarter = tid & 3;
    const int cb   = quarter * 16;
    const int rsw  = quarter << 3;

    for (int i = tid; i < 16 * CIN; i += 256) {
        int j = i >> 6, k = i & 63;
        wkv_t[j * 68 + k] = (j < 8) ? wk[k * 8 + j] : wv[k * 8 + (j - 8)];
    }
    if (tid < CIN) { lnw_s[tid] = lnw[tid]; lnb_s[tid] = lnb[tid]; }
    __syncthreads();

    float qacc[16];
#pragma unroll
    for (int c = 0; c < 16; c++) qacc[c] = 0.f;
    float macc = 0.f;

#pragma unroll
    for (int half = 0; half < 2; half++) {
        for (int i = tid; i < 1024; i += 256) {
            const int row = i >> 4, k4 = i & 15;
            float4 v = *(const float4*)(m + ((size_t)(n0 + half * 64 + row) * NRES + r) * CIN + k4 * 4);
            *(float4*)(raw + row * 68 + k4 * 4) = v;
        }
        __syncthreads();
        {
            const float4* rr = (const float4*)(raw + slot * 68 + cb);
            float s = 0.f, sq = 0.f;
#pragma unroll
            for (int k = 0; k < 4; k++) {
                float4 v4 = rr[k];
                s  += v4.x + v4.y + v4.z + v4.w;
                sq += v4.x * v4.x + v4.y * v4.y + v4.z * v4.z + v4.w * v4.w;
            }
            s  += __shfl_xor_sync(0xffffffffu, s, 1);
            sq += __shfl_xor_sync(0xffffffffu, sq, 1);
            s  += __shfl_xor_sync(0xffffffffu, s, 2);
            sq += __shfl_xor_sync(0xffffffffu, sq, 2);
            float mu = s * (1.f / CIN);
            float rs = rsqrtf(sq * (1.f / CIN) - mu * mu + 1e-5f);
            const int row_g = half * 64 + slot;

            float mv = 0.f;
            if (quarter == 0) mv = mask[(size_t)(n0 + row_g) * NRES + r];
            mv = __shfl_sync(0xffffffffu, mv, lane & ~3);
            if (quarter == 0) {
                g_maskT[(size_t)r * NSEQ + n0 + row_g] = mv;
                macc += mv;
            }

            const int rw = row_g ^ rsw;
#pragma unroll
            for (int k = 0; k < 4; k++) {
                float4 v4 = rr[k];
                float x0 = (v4.x - mu) * rs * lnw_s[cb + 4 * k + 0] + lnb_s[cb + 4 * k + 0];
                float x1 = (v4.y - mu) * rs * lnw_s[cb + 4 * k + 1] + lnb_s[cb + 4 * k + 1];
                float x2 = (v4.z - mu) * rs * lnw_s[cb + 4 * k + 2] + lnb_s[cb + 4 * k + 2];
                float x3 = (v4.w - mu) * rs * lnw_s[cb + 4 * k + 3] + lnb_s[cb + 4 * k + 3];
                buf[(cb + 4 * k + 0) * 128 + rw] = x0;
                buf[(cb + 4 * k + 1) * 128 + rw] = x1;
                buf[(cb + 4 * k + 2) * 128 + rw] = x2;
                buf[(cb + 4 * k + 3) * 128 + rw] = x3;
                qacc[4 * k + 0] += mv * x0;
                qacc[4 * k + 1] += mv * x1;
                qacc[4 * k + 2] += mv * x2;
                qacc[4 * k + 3] += mv * x3;
            }
        }
        __syncthreads();
    }

#pragma unroll
    for (int c = 0; c < 16; c++) {
        float v = qacc[c];
        v += __shfl_xor_sync(0xffffffffu, v, 4);
        v += __shfl_xor_sync(0xffffffffu, v, 8);
        v += __shfl_xor_sync(0xffffffffu, v, 16);
        qacc[c] = v;
    }
    {
        float v = wsum(macc);
        if (lane == 0) mred[warp] = v;
    }
    if (lane < 4) {
#pragma unroll
        for (int c = 0; c < 16; c++) qred[warp * 64 + lane * 16 + c] = qacc[c];
    }

    // ---- X^T store (swizzle-aware, latency overlaps kv GEMM) ----
    for (int i = tid; i < 2048; i += 256) {
        const int k = i >> 5, rc = i & 31;
        float4 v = *(const float4*)(buf + k * 128 + ((rc * 4) ^ bswz(k)));
        ((float4*)(g_xt + ((size_t)r * CIN + k) * NSEQ + n0))[rc] = v;
    }

    // ---- kv projection GEMM [128 rows x 16 cols x 64 k] ----
    {
        const int rowgrp = tid >> 4;
        const int j      = tid & 15;
        const int rowbase = rowgrp * 8;

        ull acc[4];
#pragma unroll
        for (int rp = 0; rp < 4; rp++) acc[rp] = 0ull;

#pragma unroll 4
        for (int k4 = 0; k4 < CIN; k4 += 4) {
            float4 w4 = *(const float4*)(wkv_t + j * 68 + k4);
#pragma unroll
            for (int kk = 0; kk < 4; kk++) {
                const int k = k4 + kk;
                const int rb = rowbase ^ bswz(k);
                ulonglong2 x0 = *(const ulonglong2*)(buf + k * 128 + rb);
                ulonglong2 x1 = *(const ulonglong2*)(buf + k * 128 + rb + 4);
                ull wd = dup2(kk == 0 ? w4.x : kk == 1 ? w4.y : kk == 2 ? w4.z : w4.w);
                acc[0] = fma2(x0.x, wd, acc[0]);
                acc[1] = fma2(x0.y, wd, acc[1]);
                acc[2] = fma2(x1.x, wd, acc[2]);
                acc[3] = fma2(x1.y, wd, acc[3]);
            }
        }
#pragma unroll
        for (int rp = 0; rp < 4; rp++) {
            float2 t = unpk(acc[rp]);
            const int row = rowbase + 2 * rp;
            kv_s[row * 16 + j]       = t.x;
            kv_s[(row + 1) * 16 + j] = t.y;
        }
    }
    __syncthreads();

    {
        const int n = tid >> 1, half = tid & 1;
        const float4* src = (const float4*)(kv_s + n * 16 + half * 8);
        float4 a = src[0], b = src[1];
        float* dst = (half ? g_v : g_k) + ((size_t)r * NSEQ + n0 + n) * NC;
        ((float4*)dst)[0] = a;
        ((float4*)dst)[1] = b;
    }
    if (tid < CIN) {
        float s2 = 0.f;
#pragma unroll
        for (int w = 0; w < 8; w++) s2 += qred[w * 64 + tid];
        g_qpart[((size_t)r * 16 + by) * CIN + tid] = s2;
    }
    if (tid == 64) {
        float s2 = 0.f;
#pragma unroll
        for (int w = 0; w < 8; w++) s2 += mred[w];
        g_mpart[r * 16 + by] = s2;
    }
}

// =====================================================================
// Pass 2 (R12 exact, single block per r)
// =====================================================================
__global__ void __launch_bounds__(512) pass2_kernel(const float* __restrict__ wq)
{
    const int r = blockIdx.x;
    const int tid = threadIdx.x;
    const int lane = tid & 31, warp = tid >> 5;
    const int slot = tid >> 1, hp = tid & 1;

    __shared__ float qpre[CIN];
    __shared__ float qh[CIN];
    __shared__ float msum_s;
    __shared__ float redm[16][NH];
    __shared__ float reds[16][NH];
    __shared__ float hmax_s[NH], hsum_s[NH];
    __shared__ float ored[16][CIN];

    if (tid < CIN) {
        float s = 0.f;
#pragma unroll
        for (int p = 0; p < 16; p++) s += g_qpart[((size_t)r * 16 + p) * CIN + tid];
        qpre[tid] = s;
    }
    if (tid == 64) {
        float s = 0.f;
#pragma unroll
        for (int p = 0; p < 16; p++) s += g_mpart[r * 16 + p];
        msum_s = s;
    }
    __syncthreads();
    if (tid < CIN) {
        float a = 0.f;
#pragma unroll
        for (int c = 0; c < CIN; c++) a += qpre[c] * wq[c * CIN + tid];
        qh[tid] = a * 0.3535533905932738f / (msum_s + 1e-10f);
    }
    __syncthreads();

    float l[8][4];
    float hmax[4];
#pragma unroll
    for (int h = 0; h < 4; h++) hmax[h] = -3.4e38f;

#pragma unroll
    for (int i = 0; i < 8; i++) {
        int n = i * 256 + slot;
        const float4* kp = (const float4*)(g_k + ((size_t)r * NSEQ + n) * NC);
        float4 k0 = kp[0], k1 = kp[1];
        float bias = (g_maskT[(size_t)r * NSEQ + n] - 1.f) * 1000000000.0f;
#pragma unroll
        for (int h = 0; h < 4; h++) {
            const float* q = qh + (hp * 4 + h) * NC;
            float a = q[0] * k0.x + q[1] * k0.y + q[2] * k0.z + q[3] * k0.w
                    + q[4] * k1.x + q[5] * k1.y + q[6] * k1.z + q[7] * k1.w;
            a += bias;
            l[i][h] = a;
            hmax[h] = fmaxf(hmax[h], a);
        }
    }
#pragma unroll
    for (int h = 0; h < 4; h++) {
        float v = hmax[h];
#pragma unroll
        for (int o = 16; o >= 2; o >>= 1) v = fmaxf(v, __shfl_xor_sync(0xffffffffu, v, o));
        hmax[h] = v;
    }
    if (lane < 2) {
#pragma unroll
        for (int h = 0; h < 4; h++) redm[warp][lane * 4 + h] = hmax[h];
    }
    __syncthreads();
    if (tid < NH) {
        float v = -3.4e38f;
#pragma unroll
        for (int w = 0; w < 16; w++) v = fmaxf(v, redm[w][tid]);
        hmax_s[tid] = v;
    }
    __syncthreads();

    float hsum[4];
#pragma unroll
    for (int h = 0; h < 4; h++) hsum[h] = 0.f;
    float oacc[32];
#pragma unroll
    for (int j = 0; j < 32; j++) oacc[j] = 0.f;

#pragma unroll
    for (int i = 0; i < 8; i++) {
        int n = i * 256 + slot;
        const float4* vp = (const float4*)(g_v + ((size_t)r * NSEQ + n) * NC);
        float4 v0 = vp[0], v1 = vp[1];
#pragma unroll
        for (int h = 0; h < 4; h++) {
            float p = __expf(l[i][h] - hmax_s[hp * 4 + h]);
            hsum[h] += p;
            oacc[h * 8 + 0] += p * v0.x; oacc[h * 8 + 1] += p * v0.y;
            oacc[h * 8 + 2] += p * v0.z; oacc[h * 8 + 3] += p * v0.w;
            oacc[h * 8 + 4] += p * v1.x; oacc[h * 8 + 5] += p * v1.y;
            oacc[h * 8 + 6] += p * v1.z; oacc[h * 8 + 7] += p * v1.w;
        }
    }
#pragma unroll
    for (int h = 0; h < 4; h++) {
        float v = hsum[h];
#pragma unroll
        for (int o = 16; o >= 2; o >>= 1) v += __shfl_xor_sync(0xffffffffu, v, o);
        hsum[h] = v;
    }
#pragma unroll
    for (int j = 0; j < 32; j++) {
        float v = oacc[j];
#pragma unroll
        for (int o = 16; o >= 2; o >>= 1) v += __shfl_xor_sync(0xffffffffu, v, o);
        oacc[j] = v;
    }
    if (lane < 2) {
#pragma unroll
        for (int h = 0; h < 4; h++) reds[warp][lane * 4 + h] = hsum[h];
#pragma unroll
        for (int j = 0; j < 32; j++) ored[warp][lane * 32 + j] = oacc[j];
    }
    __syncthreads();
    if (tid < NH) {
        float v = 0.f;
#pragma unroll
        for (int w = 0; w < 16; w++) v += reds[w][tid];
        hsum_s[tid] = v;
    }
    __syncthreads();
    if (tid < CIN) {
        float s2 = 0.f;
#pragma unroll
        for (int w = 0; w < 16; w++) s2 += ored[w][tid];
        g_o[r * CIN + tid] = s2 / hsum_s[tid >> 3];
    }
}

// =====================================================================
// Pass 3 v11 (hot): block = (r, 2x128 n-rows), 3 CTAs/SM (66 KB smem).
// R12 GEMM body unchanged; each CTA loops over TWO 128-row tiles,
// amortizing the weight/o/bias prologue and halving wave count.
// =====================================================================
#define P3_SMEM_FLOATS (8192 /*buf*/ + 4096 /*wg*/ + 4096 /*wo*/ + 192)
#define P3_SMEM_BYTES  (P3_SMEM_FLOATS * 4)

__global__ void __launch_bounds__(256, 3) pass3_kernel(
    const float* __restrict__ wg, const float* __restrict__ bg,
    const float* __restrict__ wo, const float* __restrict__ bo,
    float* __restrict__ out)
{
    extern __shared__ __align__(16) float sm3[];
    float* buf  = sm3;                 // 8192: X[k][128] -> Y (swizzled)
    float* wg_s = sm3 + 8192;          // 4096
    float* wo_s = sm3 + 12288;         // 4096
    float* o_s  = sm3 + 16384;
    float* bg_s = o_s + 64;
    float* bo_s = bg_s + 64;

    const int r   = blockIdx.x;
    const int tid = threadIdx.x;

    for (int i = tid; i < CIN * CIN; i += 256) { wg_s[i] = wg[i]; wo_s[i] = wo[i]; }
    if (tid < CIN) {
        o_s[tid]  = g_o[r * CIN + tid];
        bg_s[tid] = bg[tid]; bo_s[tid] = bo[tid];
    }

    const int rowgrp = tid >> 4;          // 0..15
    const int colgrp = tid & 15;          // 0..15
    const int rowbase = rowgrp * 8;
    const int colbase = colgrp * 4;
    const int sc = (colgrp & 7) << 2;     // Y swizzle for this thread's cols

#pragma unroll 1
    for (int tile = 0; tile < 2; tile++) {
        const int n0 = (blockIdx.y * 2 + tile) * 128;

        // ---- Stage A: coalesced X^T tile copy ----
#pragma unroll
        for (int t = 0; t < 8; t++) {
            const int i = t * 256 + tid;
            const int k = i >> 5, rc = i & 31;
            float4 v = ((const float4*)(g_xt + ((size_t)r * CIN + k) * NSEQ + n0))[rc];
            ((float4*)buf)[k * 32 + rc] = v;
        }
        __syncthreads();

        ull acc[4][4];

        // ================= GEMM 1: gpre = X @ Wg =================
#pragma unroll
        for (int rp = 0; rp < 4; rp++)
#pragma unroll
            for (int c = 0; c < 4; c++) acc[rp][c] = 0ull;

#pragma unroll 8
        for (int k = 0; k < CIN; k++) {
            ulonglong2 x0 = *(const ulonglong2*)(buf + k * 128 + rowbase);
            ulonglong2 x1 = *(const ulonglong2*)(buf + k * 128 + rowbase + 4);
            float4 w = *(const float4*)(wg_s + k * CIN + colbase);
            ull wd0 = dup2(w.x), wd1 = dup2(w.y), wd2 = dup2(w.z), wd3 = dup2(w.w);
            ull xs[4] = {x0.x, x0.y, x1.x, x1.y};
#pragma unroll
            for (int rp = 0; rp < 4; rp++) {
                acc[rp][0] = fma2(xs[rp], wd0, acc[rp][0]);
                acc[rp][1] = fma2(xs[rp], wd1, acc[rp][1]);
                acc[rp][2] = fma2(xs[rp], wd2, acc[rp][2]);
                acc[rp][3] = fma2(xs[rp], wd3, acc[rp][3]);
            }
        }
        __syncthreads();   // all X reads done before Y overwrites buf

        // ---- epilogue 1: y = o * sigmoid(gpre + bg) -> buf[col][row ^ sc] ----
#pragma unroll
        for (int c = 0; c < 4; c++) {
            const int col = colbase + c;
            const float bgc = bg_s[col];
            const float oc  = o_s[col];
#pragma unroll
            for (int rp = 0; rp < 4; rp++) {
                float2 t = unpk(acc[rp][c]);
                float y0 = oc / (1.f + __expf(-(t.x + bgc)));
                float y1 = oc / (1.f + __expf(-(t.y + bgc)));
                const int row = rowbase + 2 * rp;
                *(ull*)(buf + col * 128 + (row ^ sc)) = pack2(y0, y1);
            }
        }
        __syncthreads();

        // ================= GEMM 2: out = Y @ Wo =================
#pragma unroll
        for (int rp = 0; rp < 4; rp++)
#pragma unroll
            for (int c = 0; c < 4; c++) acc[rp][c] = 0ull;

#pragma unroll 8
        for (int k = 0; k < CIN; k++) {
            const int sck = ((k >> 2) & 7) << 2;
            ulonglong2 x0 = *(const ulonglong2*)(buf + k * 128 + (rowbase ^ sck));
            ulonglong2 x1 = *(const ulonglong2*)(buf + k * 128 + ((rowbase + 4) ^ sck));
            float4 w = *(const float4*)(wo_s + k * CIN + colbase);
            ull wd0 = dup2(w.x), wd1 = dup2(w.y), wd2 = dup2(w.z), wd3 = dup2(w.w);
            ull xs[4] = {x0.x, x0.y, x1.x, x1.y};
#pragma unroll
            for (int rp = 0; rp < 4; rp++) {
                acc[rp][0] = fma2(xs[rp], wd0, acc[rp][0]);
                acc[rp][1] = fma2(xs[rp], wd1, acc[rp][1]);
                acc[rp][2] = fma2(xs[rp], wd2, acc[rp][2]);
                acc[rp][3] = fma2(xs[rp], wd3, acc[rp][3]);
            }
        }

        // ---- epilogue 2: add bias, store directly to global ----
        {
            const float b0 = bo_s[colbase + 0], b1 = bo_s[colbase + 1];
            const float b2 = bo_s[colbase + 2], b3 = bo_s[colbase + 3];
#pragma unroll
            for (int rp = 0; rp < 4; rp++) {
                float2 t0 = unpk(acc[rp][0]), t1 = unpk(acc[rp][1]);
                float2 t2 = unpk(acc[rp][2]), t3 = unpk(acc[rp][3]);
                const int row = rowbase + 2 * rp;
                float4 v;
                v.x = t0.x + b0; v.y = t1.x + b1; v.z = t2.x + b2; v.w = t3.x + b3;
                *(float4*)(out + ((size_t)(n0 + row) * NRES + r) * CIN + colbase) = v;
                v.x = t0.y + b0; v.y = t1.y + b1; v.z = t2.y + b2; v.w = t3.y + b3;
                *(float4*)(out + ((size_t)(n0 + row + 1) * NRES + r) * CIN + colbase) = v;
            }
        }
        __syncthreads();   // GEMM2 buf reads done before next tile's copy
    }
}

extern "C" void kernel_launch(void* const* d_in, const int* in_sizes, int n_in,
                              void* d_out, int out_size) {
    const float* m    = (const float*)d_in[0];
    const float* mask = (const float*)d_in[1];
    const float* lnw  = (const float*)d_in[2];
    const float* lnb  = (const float*)d_in[3];
    const float* wq   = (const float*)d_in[4];
    const float* wk   = (const float*)d_in[5];
    const float* wv   = (const float*)d_in[6];
    const float* wg   = (const float*)d_in[7];
    const float* bg   = (const float*)d_in[8];
    const float* wo   = (const float*)d_in[9];
    const float* bo   = (const float*)d_in[10];
    float* out = (float*)d_out;

    cudaFuncSetAttribute(pass1_kernel,
                         cudaFuncAttributeMaxDynamicSharedMemorySize, P1_SMEM_BYTES);
    cudaFuncSetAttribute(pass3_kernel,
                         cudaFuncAttributeMaxDynamicSharedMemorySize, P3_SMEM_BYTES);

    pass1_kernel<<<dim3(NRES, 16), 256, P1_SMEM_BYTES>>>(m, mask, lnw, lnb, wk, wv);
    pass2_kernel<<<NRES, 512>>>(wq);
    pass3_kernel<<<dim3(NRES, 8), 256, P3_SMEM_BYTES>>>(wg, bg, wo, bo, out);
}

// round 16
// speedup vs baseline: 1.0320x; 1.0320x over previous
#include <cuda_runtime.h>
#include <cuda_fp16.h>

typedef unsigned long long ull;

#define NSEQ 2048
#define NRES 512
#define CIN  64
#define NH   8
#define NC   8

// ---------------- scratch (device globals: allocation-free) ----------------
__device__ __align__(16) float  g_k[(size_t)NRES * NSEQ * NC];      // 32 MB
__device__ __align__(16) float  g_v[(size_t)NRES * NSEQ * NC];      // 32 MB
__device__ __align__(16) __half g_xt[(size_t)NRES * CIN * NSEQ];    // 128 MB  X^T [r][k][n] fp16
__device__ __align__(16) float  g_maskT[(size_t)NRES * NSEQ];       // 4 MB    mask^T [r][n]
__device__ __align__(16) float  g_qpart[NRES * 16 * CIN];
__device__ __align__(16) float  g_mpart[NRES * 16];
__device__ __align__(16) float  g_o[NRES * CIN];

// ---------------- packed f32x2 helpers ----------------
__device__ __forceinline__ ull fma2(ull a, ull b, ull c) {
    ull d;
    asm("fma.rn.f32x2 %0, %1, %2, %3;" : "=l"(d) : "l"(a), "l"(b), "l"(c));
    return d;
}
__device__ __forceinline__ ull dup2(float x) {
    ull d; unsigned xi = __float_as_uint(x);
    asm("mov.b64 %0, {%1, %1};" : "=l"(d) : "r"(xi));
    return d;
}
__device__ __forceinline__ ull pack2(float lo, float hi) {
    ull d;
    asm("mov.b64 %0, {%1, %2};" : "=l"(d) : "r"(__float_as_uint(lo)), "r"(__float_as_uint(hi)));
    return d;
}
__device__ __forceinline__ float2 unpk(ull a) {
    unsigned lo, hi;
    asm("mov.b64 {%0, %1}, %2;" : "=r"(lo), "=r"(hi) : "l"(a));
    return make_float2(__uint_as_float(lo), __uint_as_float(hi));
}
__device__ __forceinline__ float wsum(float v) {
#pragma unroll
    for (int o = 16; o; o >>= 1) v += __shfl_xor_sync(0xffffffffu, v, o);
    return v;
}

// buf row swizzle: channel group (k>>4) XORs the row by 0/8/16/24.
__device__ __forceinline__ int bswz(int k) { return ((k >> 4) & 3) << 3; }

// =====================================================================
// Pass 1 (R12 + fp16 X^T store): block = (r, 128 n-rows), 4 CTAs/SM.
// =====================================================================
#define P1_SMEM_FLOATS (8192 + 4352 + 1088 + 128 + 512 + 8)
#define P1_SMEM_BYTES  (P1_SMEM_FLOATS * 4)

__global__ void __launch_bounds__(256, 4) pass1_kernel(
    const float* __restrict__ m, const float* __restrict__ mask,
    const float* __restrict__ lnw, const float* __restrict__ lnb,
    const float* __restrict__ wk, const float* __restrict__ wv)
{
    extern __shared__ __align__(16) float sm1[];
    float* buf    = sm1;                    // 8192: X[k][row ^ bswz(k)]
    float* raw    = sm1 + 8192;             // 4352: m half-tile [row][68]
    float* kv_s   = sm1 + 8192;             // 2048: kv staging (aliases raw)
    float* wkv_t  = sm1 + 12544;            // 1088
    float* lnw_s  = sm1 + 13632;
    float* lnb_s  = sm1 + 13696;
    float* qred   = sm1 + 13760;
    float* mred   = sm1 + 14272;

    const int r   = blockIdx.x;
    const int by  = blockIdx.y;
    const int n0  = by * 128;
    const int tid = threadIdx.x;
    const int lane = tid & 31, warp = tid >> 5;
    const int slot = tid >> 2, quarter = tid & 3;
    const int cb   = quarter * 16;
    const int rsw  = quarter << 3;

    for (int i = tid; i < 16 * CIN; i += 256) {
        int j = i >> 6, k = i & 63;
        wkv_t[j * 68 + k] = (j < 8) ? wk[k * 8 + j] : wv[k * 8 + (j - 8)];
    }
    if (tid < CIN) { lnw_s[tid] = lnw[tid]; lnb_s[tid] = lnb[tid]; }
    __syncthreads();

    float qacc[16];
#pragma unroll
    for (int c = 0; c < 16; c++) qacc[c] = 0.f;
    float macc = 0.f;

#pragma unroll
    for (int half = 0; half < 2; half++) {
        for (int i = tid; i < 1024; i += 256) {
            const int row = i >> 4, k4 = i & 15;
            float4 v = *(const float4*)(m + ((size_t)(n0 + half * 64 + row) * NRES + r) * CIN + k4 * 4);
            *(float4*)(raw + row * 68 + k4 * 4) = v;
        }
        __syncthreads();
        {
            const float4* rr = (const float4*)(raw + slot * 68 + cb);
            float s = 0.f, sq = 0.f;
#pragma unroll
            for (int k = 0; k < 4; k++) {
                float4 v4 = rr[k];
                s  += v4.x + v4.y + v4.z + v4.w;
                sq += v4.x * v4.x + v4.y * v4.y + v4.z * v4.z + v4.w * v4.w;
            }
            s  += __shfl_xor_sync(0xffffffffu, s, 1);
            sq += __shfl_xor_sync(0xffffffffu, sq, 1);
            s  += __shfl_xor_sync(0xffffffffu, s, 2);
            sq += __shfl_xor_sync(0xffffffffu, sq, 2);
            float mu = s * (1.f / CIN);
            float rs = rsqrtf(sq * (1.f / CIN) - mu * mu + 1e-5f);
            const int row_g = half * 64 + slot;

            float mv = 0.f;
            if (quarter == 0) mv = mask[(size_t)(n0 + row_g) * NRES + r];
            mv = __shfl_sync(0xffffffffu, mv, lane & ~3);
            if (quarter == 0) {
                g_maskT[(size_t)r * NSEQ + n0 + row_g] = mv;
                macc += mv;
            }

            const int rw = row_g ^ rsw;
#pragma unroll
            for (int k = 0; k < 4; k++) {
                float4 v4 = rr[k];
                float x0 = (v4.x - mu) * rs * lnw_s[cb + 4 * k + 0] + lnb_s[cb + 4 * k + 0];
                float x1 = (v4.y - mu) * rs * lnw_s[cb + 4 * k + 1] + lnb_s[cb + 4 * k + 1];
                float x2 = (v4.z - mu) * rs * lnw_s[cb + 4 * k + 2] + lnb_s[cb + 4 * k + 2];
                float x3 = (v4.w - mu) * rs * lnw_s[cb + 4 * k + 3] + lnb_s[cb + 4 * k + 3];
                buf[(cb + 4 * k + 0) * 128 + rw] = x0;
                buf[(cb + 4 * k + 1) * 128 + rw] = x1;
                buf[(cb + 4 * k + 2) * 128 + rw] = x2;
                buf[(cb + 4 * k + 3) * 128 + rw] = x3;
                qacc[4 * k + 0] += mv * x0;
                qacc[4 * k + 1] += mv * x1;
                qacc[4 * k + 2] += mv * x2;
                qacc[4 * k + 3] += mv * x3;
            }
        }
        __syncthreads();
    }

#pragma unroll
    for (int c = 0; c < 16; c++) {
        float v = qacc[c];
        v += __shfl_xor_sync(0xffffffffu, v, 4);
        v += __shfl_xor_sync(0xffffffffu, v, 8);
        v += __shfl_xor_sync(0xffffffffu, v, 16);
        qacc[c] = v;
    }
    {
        float v = wsum(macc);
        if (lane == 0) mred[warp] = v;
    }
    if (lane < 4) {
#pragma unroll
        for (int c = 0; c < 16; c++) qred[warp * 64 + lane * 16 + c] = qacc[c];
    }

    // ---- X^T store in fp16 (swizzle-aware; latency overlaps kv GEMM) ----
    for (int i = tid; i < 2048; i += 256) {
        const int k = i >> 5, rc = i & 31;
        float4 v = *(const float4*)(buf + k * 128 + ((rc * 4) ^ bswz(k)));
        __half2 h0 = __floats2half2_rn(v.x, v.y);
        __half2 h1 = __floats2half2_rn(v.z, v.w);
        uint2 u;
        u.x = *reinterpret_cast<unsigned*>(&h0);
        u.y = *reinterpret_cast<unsigned*>(&h1);
        ((uint2*)(g_xt + ((size_t)r * CIN + k) * NSEQ + n0))[rc] = u;
    }

    // ---- kv projection GEMM [128 rows x 16 cols x 64 k] ----
    {
        const int rowgrp = tid >> 4;
        const int j      = tid & 15;
        const int rowbase = rowgrp * 8;

        ull acc[4];
#pragma unroll
        for (int rp = 0; rp < 4; rp++) acc[rp] = 0ull;

#pragma unroll 4
        for (int k4 = 0; k4 < CIN; k4 += 4) {
            float4 w4 = *(const float4*)(wkv_t + j * 68 + k4);
#pragma unroll
            for (int kk = 0; kk < 4; kk++) {
                const int k = k4 + kk;
                const int rb = rowbase ^ bswz(k);
                ulonglong2 x0 = *(const ulonglong2*)(buf + k * 128 + rb);
                ulonglong2 x1 = *(const ulonglong2*)(buf + k * 128 + rb + 4);
                ull wd = dup2(kk == 0 ? w4.x : kk == 1 ? w4.y : kk == 2 ? w4.z : w4.w);
                acc[0] = fma2(x0.x, wd, acc[0]);
                acc[1] = fma2(x0.y, wd, acc[1]);
                acc[2] = fma2(x1.x, wd, acc[2]);
                acc[3] = fma2(x1.y, wd, acc[3]);
            }
        }
#pragma unroll
        for (int rp = 0; rp < 4; rp++) {
            float2 t = unpk(acc[rp]);
            const int row = rowbase + 2 * rp;
            kv_s[row * 16 + j]       = t.x;
            kv_s[(row + 1) * 16 + j] = t.y;
        }
    }
    __syncthreads();

    {
        const int n = tid >> 1, half = tid & 1;
        const float4* src = (const float4*)(kv_s + n * 16 + half * 8);
        float4 a = src[0], b = src[1];
        float* dst = (half ? g_v : g_k) + ((size_t)r * NSEQ + n0 + n) * NC;
        ((float4*)dst)[0] = a;
        ((float4*)dst)[1] = b;
    }
    if (tid < CIN) {
        float s2 = 0.f;
#pragma unroll
        for (int w = 0; w < 8; w++) s2 += qred[w * 64 + tid];
        g_qpart[((size_t)r * 16 + by) * CIN + tid] = s2;
    }
    if (tid == 64) {
        float s2 = 0.f;
#pragma unroll
        for (int w = 0; w < 8; w++) s2 += mred[w];
        g_mpart[r * 16 + by] = s2;
    }
}

// =====================================================================
// Pass 2 (R12 exact)
// =====================================================================
__global__ void __launch_bounds__(512) pass2_kernel(const float* __restrict__ wq)
{
    const int r = blockIdx.x;
    const int tid = threadIdx.x;
    const int lane = tid & 31, warp = tid >> 5;
    const int slot = tid >> 1, hp = tid & 1;

    __shared__ float qpre[CIN];
    __shared__ float qh[CIN];
    __shared__ float msum_s;
    __shared__ float redm[16][NH];
    __shared__ float reds[16][NH];
    __shared__ float hmax_s[NH], hsum_s[NH];
    __shared__ float ored[16][CIN];

    if (tid < CIN) {
        float s = 0.f;
#pragma unroll
        for (int p = 0; p < 16; p++) s += g_qpart[((size_t)r * 16 + p) * CIN + tid];
        qpre[tid] = s;
    }
    if (tid == 64) {
        float s = 0.f;
#pragma unroll
        for (int p = 0; p < 16; p++) s += g_mpart[r * 16 + p];
        msum_s = s;
    }
    __syncthreads();
    if (tid < CIN) {
        float a = 0.f;
#pragma unroll
        for (int c = 0; c < CIN; c++) a += qpre[c] * wq[c * CIN + tid];
        qh[tid] = a * 0.3535533905932738f / (msum_s + 1e-10f);
    }
    __syncthreads();

    float l[8][4];
    float hmax[4];
#pragma unroll
    for (int h = 0; h < 4; h++) hmax[h] = -3.4e38f;

#pragma unroll
    for (int i = 0; i < 8; i++) {
        int n = i * 256 + slot;
        const float4* kp = (const float4*)(g_k + ((size_t)r * NSEQ + n) * NC);
        float4 k0 = kp[0], k1 = kp[1];
        float bias = (g_maskT[(size_t)r * NSEQ + n] - 1.f) * 1000000000.0f;
#pragma unroll
        for (int h = 0; h < 4; h++) {
            const float* q = qh + (hp * 4 + h) * NC;
            float a = q[0] * k0.x + q[1] * k0.y + q[2] * k0.z + q[3] * k0.w
                    + q[4] * k1.x + q[5] * k1.y + q[6] * k1.z + q[7] * k1.w;
            a += bias;
            l[i][h] = a;
            hmax[h] = fmaxf(hmax[h], a);
        }
    }
#pragma unroll
    for (int h = 0; h < 4; h++) {
        float v = hmax[h];
#pragma unroll
        for (int o = 16; o >= 2; o >>= 1) v = fmaxf(v, __shfl_xor_sync(0xffffffffu, v, o));
        hmax[h] = v;
    }
    if (lane < 2) {
#pragma unroll
        for (int h = 0; h < 4; h++) redm[warp][lane * 4 + h] = hmax[h];
    }
    __syncthreads();
    if (tid < NH) {
        float v = -3.4e38f;
#pragma unroll
        for (int w = 0; w < 16; w++) v = fmaxf(v, redm[w][tid]);
        hmax_s[tid] = v;
    }
    __syncthreads();

    float hsum[4];
#pragma unroll
    for (int h = 0; h < 4; h++) hsum[h] = 0.f;
    float oacc[32];
#pragma unroll
    for (int j = 0; j < 32; j++) oacc[j] = 0.f;

#pragma unroll
    for (int i = 0; i < 8; i++) {
        int n = i * 256 + slot;
        const float4* vp = (const float4*)(g_v + ((size_t)r * NSEQ + n) * NC);
        float4 v0 = vp[0], v1 = vp[1];
#pragma unroll
        for (int h = 0; h < 4; h++) {
            float p = __expf(l[i][h] - hmax_s[hp * 4 + h]);
            hsum[h] += p;
            oacc[h * 8 + 0] += p * v0.x; oacc[h * 8 + 1] += p * v0.y;
            oacc[h * 8 + 2] += p * v0.z; oacc[h * 8 + 3] += p * v0.w;
            oacc[h * 8 + 4] += p * v1.x; oacc[h * 8 + 5] += p * v1.y;
            oacc[h * 8 + 6] += p * v1.z; oacc[h * 8 + 7] += p * v1.w;
        }
    }
#pragma unroll
    for (int h = 0; h < 4; h++) {
        float v = hsum[h];
#pragma unroll
        for (int o = 16; o >= 2; o >>= 1) v += __shfl_xor_sync(0xffffffffu, v, o);
        hsum[h] = v;
    }
#pragma unroll
    for (int j = 0; j < 32; j++) {
        float v = oacc[j];
#pragma unroll
        for (int o = 16; o >= 2; o >>= 1) v += __shfl_xor_sync(0xffffffffu, v, o);
        oacc[j] = v;
    }
    if (lane < 2) {
#pragma unroll
        for (int h = 0; h < 4; h++) reds[warp][lane * 4 + h] = hsum[h];
#pragma unroll
        for (int j = 0; j < 32; j++) ored[warp][lane * 32 + j] = oacc[j];
    }
    __syncthreads();
    if (tid < NH) {
        float v = 0.f;
#pragma unroll
        for (int w = 0; w < 16; w++) v += reds[w][tid];
        hsum_s[tid] = v;
    }
    __syncthreads();
    if (tid < CIN) {
        float s2 = 0.f;
#pragma unroll
        for (int w = 0; w < 16; w++) s2 += ored[w][tid];
        g_o[r * CIN + tid] = s2 / hsum_s[tid >> 3];
    }
}

// =====================================================================
// Pass 3 (R12 + fp16 X^T load): block = (r, 128 n-rows), 3 CTAs/SM.
// Thread tile 8 rows x 4 cols x 64 k. Y XOR-swizzled. k-loops unroll 8.
// =====================================================================
#define P3_SMEM_FLOATS (8192 /*buf*/ + 4096 /*wg*/ + 4096 /*wo*/ + 192)
#define P3_SMEM_BYTES  (P3_SMEM_FLOATS * 4)

__global__ void __launch_bounds__(256, 3) pass3_kernel(
    const float* __restrict__ wg, const float* __restrict__ bg,
    const float* __restrict__ wo, const float* __restrict__ bo,
    float* __restrict__ out)
{
    extern __shared__ __align__(16) float sm3[];
    float* buf  = sm3;                 // 8192: X[k][128] -> Y (swizzled)
    float* wg_s = sm3 + 8192;          // 4096
    float* wo_s = sm3 + 12288;         // 4096
    float* o_s  = sm3 + 16384;
    float* bg_s = o_s + 64;
    float* bo_s = bg_s + 64;

    const int r   = blockIdx.x;
    const int tid = threadIdx.x;
    const int n0  = blockIdx.y * 128;

    for (int i = tid; i < CIN * CIN; i += 256) { wg_s[i] = wg[i]; wo_s[i] = wo[i]; }
    if (tid < CIN) {
        o_s[tid]  = g_o[r * CIN + tid];
        bg_s[tid] = bg[tid]; bo_s[tid] = bo[tid];
    }

    // ---- Stage A: coalesced fp16 X^T tile copy -> fp32 smem ----
#pragma unroll
    for (int t = 0; t < 8; t++) {
        const int i = t * 256 + tid;
        const int k = i >> 5, rc = i & 31;
        uint2 u = ((const uint2*)(g_xt + ((size_t)r * CIN + k) * NSEQ + n0))[rc];
        __half2 h0 = *reinterpret_cast<__half2*>(&u.x);
        __half2 h1 = *reinterpret_cast<__half2*>(&u.y);
        float2 f0 = __half22float2(h0);
        float2 f1 = __half22float2(h1);
        float4 v; v.x = f0.x; v.y = f0.y; v.z = f1.x; v.w = f1.y;
        ((float4*)buf)[k * 32 + rc] = v;
    }
    __syncthreads();

    const int rowgrp = tid >> 4;          // 0..15
    const int colgrp = tid & 15;          // 0..15
    const int rowbase = rowgrp * 8;
    const int colbase = colgrp * 4;
    const int sc = (colgrp & 7) << 2;     // Y swizzle for this thread's cols

    ull acc[4][4];

    // ================= GEMM 1: gpre = X @ Wg =================
#pragma unroll
    for (int rp = 0; rp < 4; rp++)
#pragma unroll
        for (int c = 0; c < 4; c++) acc[rp][c] = 0ull;

#pragma unroll 8
    for (int k = 0; k < CIN; k++) {
        ulonglong2 x0 = *(const ulonglong2*)(buf + k * 128 + rowbase);
        ulonglong2 x1 = *(const ulonglong2*)(buf + k * 128 + rowbase + 4);
        float4 w = *(const float4*)(wg_s + k * CIN + colbase);
        ull wd0 = dup2(w.x), wd1 = dup2(w.y), wd2 = dup2(w.z), wd3 = dup2(w.w);
        ull xs[4] = {x0.x, x0.y, x1.x, x1.y};
#pragma unroll
        for (int rp = 0; rp < 4; rp++) {
            acc[rp][0] = fma2(xs[rp], wd0, acc[rp][0]);
            acc[rp][1] = fma2(xs[rp], wd1, acc[rp][1]);
            acc[rp][2] = fma2(xs[rp], wd2, acc[rp][2]);
            acc[rp][3] = fma2(xs[rp], wd3, acc[rp][3]);
        }
    }
    __syncthreads();   // all X reads done before Y overwrites buf

    // ---- epilogue 1: y = o * sigmoid(gpre + bg) -> buf[col][row ^ sc] ----
#pragma unroll
    for (int c = 0; c < 4; c++) {
        const int col = colbase + c;
        const float bgc = bg_s[col];
        const float oc  = o_s[col];
#pragma unroll
        for (int rp = 0; rp < 4; rp++) {
            float2 t = unpk(acc[rp][c]);
            float y0 = oc / (1.f + __expf(-(t.x + bgc)));
            float y1 = oc / (1.f + __expf(-(t.y + bgc)));
            const int row = rowbase + 2 * rp;
            *(ull*)(buf + col * 128 + (row ^ sc)) = pack2(y0, y1);
        }
    }
    __syncthreads();

    // ================= GEMM 2: out = Y @ Wo =================
#pragma unroll
    for (int rp = 0; rp < 4; rp++)
#pragma unroll
        for (int c = 0; c < 4; c++) acc[rp][c] = 0ull;

#pragma unroll 8
    for (int k = 0; k < CIN; k++) {
        const int sck = ((k >> 2) & 7) << 2;
        ulonglong2 x0 = *(const ulonglong2*)(buf + k * 128 + (rowbase ^ sck));
        ulonglong2 x1 = *(const ulonglong2*)(buf + k * 128 + ((rowbase + 4) ^ sck));
        float4 w = *(const float4*)(wo_s + k * CIN + colbase);
        ull wd0 = dup2(w.x), wd1 = dup2(w.y), wd2 = dup2(w.z), wd3 = dup2(w.w);
        ull xs[4] = {x0.x, x0.y, x1.x, x1.y};
#pragma unroll
        for (int rp = 0; rp < 4; rp++) {
            acc[rp][0] = fma2(xs[rp], wd0, acc[rp][0]);
            acc[rp][1] = fma2(xs[rp], wd1, acc[rp][1]);
            acc[rp][2] = fma2(xs[rp], wd2, acc[rp][2]);
            acc[rp][3] = fma2(xs[rp], wd3, acc[rp][3]);
        }
    }

    // ---- epilogue 2: add bias, store directly to global ----
    {
        const float b0 = bo_s[colbase + 0], b1 = bo_s[colbase + 1];
        const float b2 = bo_s[colbase + 2], b3 = bo_s[colbase + 3];
#pragma unroll
        for (int rp = 0; rp < 4; rp++) {
            float2 t0 = unpk(acc[rp][0]), t1 = unpk(acc[rp][1]);
            float2 t2 = unpk(acc[rp][2]), t3 = unpk(acc[rp][3]);
            const int row = rowbase + 2 * rp;
            float4 v;
            v.x = t0.x + b0; v.y = t1.x + b1; v.z = t2.x + b2; v.w = t3.x + b3;
            *(float4*)(out + ((size_t)(n0 + row) * NRES + r) * CIN + colbase) = v;
            v.x = t0.y + b0; v.y = t1.y + b1; v.z = t2.y + b2; v.w = t3.y + b3;
            *(float4*)(out + ((size_t)(n0 + row + 1) * NRES + r) * CIN + colbase) = v;
        }
    }
}

extern "C" void kernel_launch(void* const* d_in, const int* in_sizes, int n_in,
                              void* d_out, int out_size) {
    const float* m    = (const float*)d_in[0];
    const float* mask = (const float*)d_in[1];
    const float* lnw  = (const float*)d_in[2];
    const float* lnb  = (const float*)d_in[3];
    const float* wq   = (const float*)d_in[4];
    const float* wk   = (const float*)d_in[5];
    const float* wv   = (const float*)d_in[6];
    const float* wg   = (const float*)d_in[7];
    const float* bg   = (const float*)d_in[8];
    const float* wo   = (const float*)d_in[9];
    const float* bo   = (const float*)d_in[10];
    float* out = (float*)d_out;

    cudaFuncSetAttribute(pass1_kernel,
                         cudaFuncAttributeMaxDynamicSharedMemorySize, P1_SMEM_BYTES);
    cudaFuncSetAttribute(pass3_kernel,
                         cudaFuncAttributeMaxDynamicSharedMemorySize, P3_SMEM_BYTES);

    pass1_kernel<<<dim3(NRES, 16), 256, P1_SMEM_BYTES>>>(m, mask, lnw, lnb, wk, wv);
    pass2_kernel<<<NRES, 512>>>(wq);
    pass3_kernel<<<dim3(NRES, 16), 256, P3_SMEM_BYTES>>>(wg, bg, wo, bo, out);
}

// round 17
// speedup vs baseline: 1.0530x; 1.0203x over previous
#include <cuda_runtime.h>
#include <cuda_fp16.h>

typedef unsigned long long ull;

#define NSEQ 2048
#define NRES 512
#define CIN  64
#define NH   8
#define NC   8

// ---------------- scratch (device globals: allocation-free) ----------------
__device__ __align__(16) __half g_k[(size_t)NRES * NSEQ * NC];      // 16 MB
__device__ __align__(16) __half g_v[(size_t)NRES * NSEQ * NC];      // 16 MB
__device__ __align__(16) __half g_xt[(size_t)NRES * CIN * NSEQ];    // 128 MB  X^T [r][k][n] fp16
__device__ __align__(16) float  g_maskT[(size_t)NRES * NSEQ];       // 4 MB    mask^T [r][n]
__device__ __align__(16) float  g_qpart[NRES * 16 * CIN];
__device__ __align__(16) float  g_mpart[NRES * 16];
__device__ __align__(16) float  g_o[NRES * CIN];

// ---------------- packed f32x2 helpers ----------------
__device__ __forceinline__ ull fma2(ull a, ull b, ull c) {
    ull d;
    asm("fma.rn.f32x2 %0, %1, %2, %3;" : "=l"(d) : "l"(a), "l"(b), "l"(c));
    return d;
}
__device__ __forceinline__ ull dup2(float x) {
    ull d; unsigned xi = __float_as_uint(x);
    asm("mov.b64 %0, {%1, %1};" : "=l"(d) : "r"(xi));
    return d;
}
__device__ __forceinline__ ull pack2(float lo, float hi) {
    ull d;
    asm("mov.b64 %0, {%1, %2};" : "=l"(d) : "r"(__float_as_uint(lo)), "r"(__float_as_uint(hi)));
    return d;
}
__device__ __forceinline__ float2 unpk(ull a) {
    unsigned lo, hi;
    asm("mov.b64 {%0, %1}, %2;" : "=r"(lo), "=r"(hi) : "l"(a));
    return make_float2(__uint_as_float(lo), __uint_as_float(hi));
}
__device__ __forceinline__ float wsum(float v) {
#pragma unroll
    for (int o = 16; o; o >>= 1) v += __shfl_xor_sync(0xffffffffu, v, o);
    return v;
}

// buf row swizzle: channel group (k>>4) XORs the row by 0/8/16/24.
__device__ __forceinline__ int bswz(int k) { return ((k >> 4) & 3) << 3; }

// =====================================================================
// Pass 1: block = (r, 128 n-rows), 4 CTAs/SM. fp16 X^T + fp16 k/v.
// =====================================================================
#define P1_SMEM_FLOATS (8192 + 4352 + 1088 + 128 + 512 + 8)
#define P1_SMEM_BYTES  (P1_SMEM_FLOATS * 4)

__global__ void __launch_bounds__(256, 4) pass1_kernel(
    const float* __restrict__ m, const float* __restrict__ mask,
    const float* __restrict__ lnw, const float* __restrict__ lnb,
    const float* __restrict__ wk, const float* __restrict__ wv)
{
    extern __shared__ __align__(16) float sm1[];
    float* buf    = sm1;                    // 8192: X[k][row ^ bswz(k)]
    float* raw    = sm1 + 8192;             // 4352: m half-tile [row][68]
    float* kv_s   = sm1 + 8192;             // 2048: kv staging (aliases raw)
    float* wkv_t  = sm1 + 12544;            // 1088
    float* lnw_s  = sm1 + 13632;
    float* lnb_s  = sm1 + 13696;
    float* qred   = sm1 + 13760;
    float* mred   = sm1 + 14272;

    const int r   = blockIdx.x;
    const int by  = blockIdx.y;
    const int n0  = by * 128;
    const int tid = threadIdx.x;
    const int lane = tid & 31, warp = tid >> 5;
    const int slot = tid >> 2, quarter = tid & 3;
    const int cb   = quarter * 16;
    const int rsw  = quarter << 3;

    for (int i = tid; i < 16 * CIN; i += 256) {
        int j = i >> 6, k = i & 63;
        wkv_t[j * 68 + k] = (j < 8) ? wk[k * 8 + j] : wv[k * 8 + (j - 8)];
    }
    if (tid < CIN) { lnw_s[tid] = lnw[tid]; lnb_s[tid] = lnb[tid]; }
    __syncthreads();

    float qacc[16];
#pragma unroll
    for (int c = 0; c < 16; c++) qacc[c] = 0.f;
    float macc = 0.f;

#pragma unroll
    for (int half = 0; half < 2; half++) {
        for (int i = tid; i < 1024; i += 256) {
            const int row = i >> 4, k4 = i & 15;
            float4 v = *(const float4*)(m + ((size_t)(n0 + half * 64 + row) * NRES + r) * CIN + k4 * 4);
            *(float4*)(raw + row * 68 + k4 * 4) = v;
        }
        __syncthreads();
        {
            const float4* rr = (const float4*)(raw + slot * 68 + cb);
            float s = 0.f, sq = 0.f;
#pragma unroll
            for (int k = 0; k < 4; k++) {
                float4 v4 = rr[k];
                s  += v4.x + v4.y + v4.z + v4.w;
                sq += v4.x * v4.x + v4.y * v4.y + v4.z * v4.z + v4.w * v4.w;
            }
            s  += __shfl_xor_sync(0xffffffffu, s, 1);
            sq += __shfl_xor_sync(0xffffffffu, sq, 1);
            s  += __shfl_xor_sync(0xffffffffu, s, 2);
            sq += __shfl_xor_sync(0xffffffffu, sq, 2);
            float mu = s * (1.f / CIN);
            float rs = rsqrtf(sq * (1.f / CIN) - mu * mu + 1e-5f);
            const int row_g = half * 64 + slot;

            float mv = 0.f;
            if (quarter == 0) mv = mask[(size_t)(n0 + row_g) * NRES + r];
            mv = __shfl_sync(0xffffffffu, mv, lane & ~3);
            if (quarter == 0) {
                g_maskT[(size_t)r * NSEQ + n0 + row_g] = mv;
                macc += mv;
            }

            const int rw = row_g ^ rsw;
#pragma unroll
            for (int k = 0; k < 4; k++) {
                float4 v4 = rr[k];
                float x0 = (v4.x - mu) * rs * lnw_s[cb + 4 * k + 0] + lnb_s[cb + 4 * k + 0];
                float x1 = (v4.y - mu) * rs * lnw_s[cb + 4 * k + 1] + lnb_s[cb + 4 * k + 1];
                float x2 = (v4.z - mu) * rs * lnw_s[cb + 4 * k + 2] + lnb_s[cb + 4 * k + 2];
                float x3 = (v4.w - mu) * rs * lnw_s[cb + 4 * k + 3] + lnb_s[cb + 4 * k + 3];
                buf[(cb + 4 * k + 0) * 128 + rw] = x0;
                buf[(cb + 4 * k + 1) * 128 + rw] = x1;
                buf[(cb + 4 * k + 2) * 128 + rw] = x2;
                buf[(cb + 4 * k + 3) * 128 + rw] = x3;
                qacc[4 * k + 0] += mv * x0;
                qacc[4 * k + 1] += mv * x1;
                qacc[4 * k + 2] += mv * x2;
                qacc[4 * k + 3] += mv * x3;
            }
        }
        __syncthreads();
    }

#pragma unroll
    for (int c = 0; c < 16; c++) {
        float v = qacc[c];
        v += __shfl_xor_sync(0xffffffffu, v, 4);
        v += __shfl_xor_sync(0xffffffffu, v, 8);
        v += __shfl_xor_sync(0xffffffffu, v, 16);
        qacc[c] = v;
    }
    {
        float v = wsum(macc);
        if (lane == 0) mred[warp] = v;
    }
    if (lane < 4) {
#pragma unroll
        for (int c = 0; c < 16; c++) qred[warp * 64 + lane * 16 + c] = qacc[c];
    }

    // ---- X^T store in fp16 (swizzle-aware; latency overlaps kv GEMM) ----
    for (int i = tid; i < 2048; i += 256) {
        const int k = i >> 5, rc = i & 31;
        float4 v = *(const float4*)(buf + k * 128 + ((rc * 4) ^ bswz(k)));
        __half2 h0 = __floats2half2_rn(v.x, v.y);
        __half2 h1 = __floats2half2_rn(v.z, v.w);
        uint2 u;
        u.x = *reinterpret_cast<unsigned*>(&h0);
        u.y = *reinterpret_cast<unsigned*>(&h1);
        ((uint2*)(g_xt + ((size_t)r * CIN + k) * NSEQ + n0))[rc] = u;
    }

    // ---- kv projection GEMM [128 rows x 16 cols x 64 k] ----
    {
        const int rowgrp = tid >> 4;
        const int j      = tid & 15;
        const int rowbase = rowgrp * 8;

        ull acc[4];
#pragma unroll
        for (int rp = 0; rp < 4; rp++) acc[rp] = 0ull;

#pragma unroll 4
        for (int k4 = 0; k4 < CIN; k4 += 4) {
            float4 w4 = *(const float4*)(wkv_t + j * 68 + k4);
#pragma unroll
            for (int kk = 0; kk < 4; kk++) {
                const int k = k4 + kk;
                const int rb = rowbase ^ bswz(k);
                ulonglong2 x0 = *(const ulonglong2*)(buf + k * 128 + rb);
                ulonglong2 x1 = *(const ulonglong2*)(buf + k * 128 + rb + 4);
                ull wd = dup2(kk == 0 ? w4.x : kk == 1 ? w4.y : kk == 2 ? w4.z : w4.w);
                acc[0] = fma2(x0.x, wd, acc[0]);
                acc[1] = fma2(x0.y, wd, acc[1]);
                acc[2] = fma2(x1.x, wd, acc[2]);
                acc[3] = fma2(x1.y, wd, acc[3]);
            }
        }
#pragma unroll
        for (int rp = 0; rp < 4; rp++) {
            float2 t = unpk(acc[rp]);
            const int row = rowbase + 2 * rp;
            kv_s[row * 16 + j]       = t.x;
            kv_s[(row + 1) * 16 + j] = t.y;
        }
    }
    __syncthreads();

    // ---- coalesced fp16 kv store ----
    {
        const int n = tid >> 1, half = tid & 1;
        const float4* src = (const float4*)(kv_s + n * 16 + half * 8);
        float4 a = src[0], b = src[1];
        __half2 h0 = __floats2half2_rn(a.x, a.y);
        __half2 h1 = __floats2half2_rn(a.z, a.w);
        __half2 h2 = __floats2half2_rn(b.x, b.y);
        __half2 h3 = __floats2half2_rn(b.z, b.w);
        uint4 u;
        u.x = *reinterpret_cast<unsigned*>(&h0);
        u.y = *reinterpret_cast<unsigned*>(&h1);
        u.z = *reinterpret_cast<unsigned*>(&h2);
        u.w = *reinterpret_cast<unsigned*>(&h3);
        __half* dst = (half ? g_v : g_k) + ((size_t)r * NSEQ + n0 + n) * NC;
        *(uint4*)dst = u;
    }
    if (tid < CIN) {
        float s2 = 0.f;
#pragma unroll
        for (int w = 0; w < 8; w++) s2 += qred[w * 64 + tid];
        g_qpart[((size_t)r * 16 + by) * CIN + tid] = s2;
    }
    if (tid == 64) {
        float s2 = 0.f;
#pragma unroll
        for (int w = 0; w < 8; w++) s2 += mred[w];
        g_mpart[r * 16 + by] = s2;
    }
}

// =====================================================================
// Pass 2: fp16 k/v loads (one LDG.128 per row per tensor).
// =====================================================================
__global__ void __launch_bounds__(512) pass2_kernel(const float* __restrict__ wq)
{
    const int r = blockIdx.x;
    const int tid = threadIdx.x;
    const int lane = tid & 31, warp = tid >> 5;
    const int slot = tid >> 1, hp = tid & 1;

    __shared__ float qpre[CIN];
    __shared__ float qh[CIN];
    __shared__ float msum_s;
    __shared__ float redm[16][NH];
    __shared__ float reds[16][NH];
    __shared__ float hmax_s[NH], hsum_s[NH];
    __shared__ float ored[16][CIN];

    if (tid < CIN) {
        float s = 0.f;
#pragma unroll
        for (int p = 0; p < 16; p++) s += g_qpart[((size_t)r * 16 + p) * CIN + tid];
        qpre[tid] = s;
    }
    if (tid == 64) {
        float s = 0.f;
#pragma unroll
        for (int p = 0; p < 16; p++) s += g_mpart[r * 16 + p];
        msum_s = s;
    }
    __syncthreads();
    if (tid < CIN) {
        float a = 0.f;
#pragma unroll
        for (int c = 0; c < CIN; c++) a += qpre[c] * wq[c * CIN + tid];
        qh[tid] = a * 0.3535533905932738f / (msum_s + 1e-10f);
    }
    __syncthreads();

    float l[8][4];
    float hmax[4];
#pragma unroll
    for (int h = 0; h < 4; h++) hmax[h] = -3.4e38f;

#pragma unroll
    for (int i = 0; i < 8; i++) {
        int n = i * 256 + slot;
        uint4 u = *(const uint4*)(g_k + ((size_t)r * NSEQ + n) * NC);
        const __half2* hpk = (const __half2*)&u;
        float2 f0 = __half22float2(hpk[0]);
        float2 f1 = __half22float2(hpk[1]);
        float2 f2 = __half22float2(hpk[2]);
        float2 f3 = __half22float2(hpk[3]);
        float bias = (g_maskT[(size_t)r * NSEQ + n] - 1.f) * 1000000000.0f;
#pragma unroll
        for (int h = 0; h < 4; h++) {
            const float* q = qh + (hp * 4 + h) * NC;
            float a = q[0] * f0.x + q[1] * f0.y + q[2] * f1.x + q[3] * f1.y
                    + q[4] * f2.x + q[5] * f2.y + q[6] * f3.x + q[7] * f3.y;
            a += bias;
            l[i][h] = a;
            hmax[h] = fmaxf(hmax[h], a);
        }
    }
#pragma unroll
    for (int h = 0; h < 4; h++) {
        float v = hmax[h];
#pragma unroll
        for (int o = 16; o >= 2; o >>= 1) v = fmaxf(v, __shfl_xor_sync(0xffffffffu, v, o));
        hmax[h] = v;
    }
    if (lane < 2) {
#pragma unroll
        for (int h = 0; h < 4; h++) redm[warp][lane * 4 + h] = hmax[h];
    }
    __syncthreads();
    if (tid < NH) {
        float v = -3.4e38f;
#pragma unroll
        for (int w = 0; w < 16; w++) v = fmaxf(v, redm[w][tid]);
        hmax_s[tid] = v;
    }
    __syncthreads();

    float hsum[4];
#pragma unroll
    for (int h = 0; h < 4; h++) hsum[h] = 0.f;
    float oacc[32];
#pragma unroll
    for (int j = 0; j < 32; j++) oacc[j] = 0.f;

#pragma unroll
    for (int i = 0; i < 8; i++) {
        int n = i * 256 + slot;
        uint4 u = *(const uint4*)(g_v + ((size_t)r * NSEQ + n) * NC);
        const __half2* hpv = (const __half2*)&u;
        float2 f0 = __half22float2(hpv[0]);
        float2 f1 = __half22float2(hpv[1]);
        float2 f2 = __half22float2(hpv[2]);
        float2 f3 = __half22float2(hpv[3]);
#pragma unroll
        for (int h = 0; h < 4; h++) {
            float p = __expf(l[i][h] - hmax_s[hp * 4 + h]);
            hsum[h] += p;
            oacc[h * 8 + 0] += p * f0.x; oacc[h * 8 + 1] += p * f0.y;
            oacc[h * 8 + 2] += p * f1.x; oacc[h * 8 + 3] += p * f1.y;
            oacc[h * 8 + 4] += p * f2.x; oacc[h * 8 + 5] += p * f2.y;
            oacc[h * 8 + 6] += p * f3.x; oacc[h * 8 + 7] += p * f3.y;
        }
    }
#pragma unroll
    for (int h = 0; h < 4; h++) {
        float v = hsum[h];
#pragma unroll
        for (int o = 16; o >= 2; o >>= 1) v += __shfl_xor_sync(0xffffffffu, v, o);
        hsum[h] = v;
    }
#pragma unroll
    for (int j = 0; j < 32; j++) {
        float v = oacc[j];
#pragma unroll
        for (int o = 16; o >= 2; o >>= 1) v += __shfl_xor_sync(0xffffffffu, v, o);
        oacc[j] = v;
    }
    if (lane < 2) {
#pragma unroll
        for (int h = 0; h < 4; h++) reds[warp][lane * 4 + h] = hsum[h];
#pragma unroll
        for (int j = 0; j < 32; j++) ored[warp][lane * 32 + j] = oacc[j];
    }
    __syncthreads();
    if (tid < NH) {
        float v = 0.f;
#pragma unroll
        for (int w = 0; w < 16; w++) v += reds[w][tid];
        hsum_s[tid] = v;
    }
    __syncthreads();
    if (tid < CIN) {
        float s2 = 0.f;
#pragma unroll
        for (int w = 0; w < 16; w++) s2 += ored[w][tid];
        g_o[r * CIN + tid] = s2 / hsum_s[tid >> 3];
    }
}

// =====================================================================
// Pass 3 (R16 exact): block = (r, 128 n-rows), 3 CTAs/SM.
// =====================================================================
#define P3_SMEM_FLOATS (8192 /*buf*/ + 4096 /*wg*/ + 4096 /*wo*/ + 192)
#define P3_SMEM_BYTES  (P3_SMEM_FLOATS * 4)

__global__ void __launch_bounds__(256, 3) pass3_kernel(
    const float* __restrict__ wg, const float* __restrict__ bg,
    const float* __restrict__ wo, const float* __restrict__ bo,
    float* __restrict__ out)
{
    extern __shared__ __align__(16) float sm3[];
    float* buf  = sm3;                 // 8192: X[k][128] -> Y (swizzled)
    float* wg_s = sm3 + 8192;          // 4096
    float* wo_s = sm3 + 12288;         // 4096
    float* o_s  = sm3 + 16384;
    float* bg_s = o_s + 64;
    float* bo_s = bg_s + 64;

    const int r   = blockIdx.x;
    const int tid = threadIdx.x;
    const int n0  = blockIdx.y * 128;

    for (int i = tid; i < CIN * CIN; i += 256) { wg_s[i] = wg[i]; wo_s[i] = wo[i]; }
    if (tid < CIN) {
        o_s[tid]  = g_o[r * CIN + tid];
        bg_s[tid] = bg[tid]; bo_s[tid] = bo[tid];
    }

    // ---- Stage A: coalesced fp16 X^T tile copy -> fp32 smem ----
#pragma unroll
    for (int t = 0; t < 8; t++) {
        const int i = t * 256 + tid;
        const int k = i >> 5, rc = i & 31;
        uint2 u = ((const uint2*)(g_xt + ((size_t)r * CIN + k) * NSEQ + n0))[rc];
        __half2 h0 = *reinterpret_cast<__half2*>(&u.x);
        __half2 h1 = *reinterpret_cast<__half2*>(&u.y);
        float2 f0 = __half22float2(h0);
        float2 f1 = __half22float2(h1);
        float4 v; v.x = f0.x; v.y = f0.y; v.z = f1.x; v.w = f1.y;
        ((float4*)buf)[k * 32 + rc] = v;
    }
    __syncthreads();

    const int rowgrp = tid >> 4;          // 0..15
    const int colgrp = tid & 15;          // 0..15
    const int rowbase = rowgrp * 8;
    const int colbase = colgrp * 4;
    const int sc = (colgrp & 7) << 2;     // Y swizzle for this thread's cols

    ull acc[4][4];

    // ================= GEMM 1: gpre = X @ Wg =================
#pragma unroll
    for (int rp = 0; rp < 4; rp++)
#pragma unroll
        for (int c = 0; c < 4; c++) acc[rp][c] = 0ull;

#pragma unroll 8
    for (int k = 0; k < CIN; k++) {
        ulonglong2 x0 = *(const ulonglong2*)(buf + k * 128 + rowbase);
        ulonglong2 x1 = *(const ulonglong2*)(buf + k * 128 + rowbase + 4);
        float4 w = *(const float4*)(wg_s + k * CIN + colbase);
        ull wd0 = dup2(w.x), wd1 = dup2(w.y), wd2 = dup2(w.z), wd3 = dup2(w.w);
        ull xs[4] = {x0.x, x0.y, x1.x, x1.y};
#pragma unroll
        for (int rp = 0; rp < 4; rp++) {
            acc[rp][0] = fma2(xs[rp], wd0, acc[rp][0]);
            acc[rp][1] = fma2(xs[rp], wd1, acc[rp][1]);
            acc[rp][2] = fma2(xs[rp], wd2, acc[rp][2]);
            acc[rp][3] = fma2(xs[rp], wd3, acc[rp][3]);
        }
    }
    __syncthreads();   // all X reads done before Y overwrites buf

    // ---- epilogue 1: y = o * sigmoid(gpre + bg) -> buf[col][row ^ sc] ----
#pragma unroll
    for (int c = 0; c < 4; c++) {
        const int col = colbase + c;
        const float bgc = bg_s[col];
        const float oc  = o_s[col];
#pragma unroll
        for (int rp = 0; rp < 4; rp++) {
            float2 t = unpk(acc[rp][c]);
            float y0 = oc / (1.f + __expf(-(t.x + bgc)));
            float y1 = oc / (1.f + __expf(-(t.y + bgc)));
            const int row = rowbase + 2 * rp;
            *(ull*)(buf + col * 128 + (row ^ sc)) = pack2(y0, y1);
        }
    }
    __syncthreads();

    // ================= GEMM 2: out = Y @ Wo =================
#pragma unroll
    for (int rp = 0; rp < 4; rp++)
#pragma unroll
        for (int c = 0; c < 4; c++) acc[rp][c] = 0ull;

#pragma unroll 8
    for (int k = 0; k < CIN; k++) {
        const int sck = ((k >> 2) & 7) << 2;
        ulonglong2 x0 = *(const ulonglong2*)(buf + k * 128 + (rowbase ^ sck));
        ulonglong2 x1 = *(const ulonglong2*)(buf + k * 128 + ((rowbase + 4) ^ sck));
        float4 w = *(const float4*)(wo_s + k * CIN + colbase);
        ull wd0 = dup2(w.x), wd1 = dup2(w.y), wd2 = dup2(w.z), wd3 = dup2(w.w);
        ull xs[4] = {x0.x, x0.y, x1.x, x1.y};
#pragma unroll
        for (int rp = 0; rp < 4; rp++) {
            acc[rp][0] = fma2(xs[rp], wd0, acc[rp][0]);
            acc[rp][1] = fma2(xs[rp], wd1, acc[rp][1]);
            acc[rp][2] = fma2(xs[rp], wd2, acc[rp][2]);
            acc[rp][3] = fma2(xs[rp], wd3, acc[rp][3]);
        }
    }

    // ---- epilogue 2: add bias, store directly to global ----
    {
        const float b0 = bo_s[colbase + 0], b1 = bo_s[colbase + 1];
        const float b2 = bo_s[colbase + 2], b3 = bo_s[colbase + 3];
#pragma unroll
        for (int rp = 0; rp < 4; rp++) {
            float2 t0 = unpk(acc[rp][0]), t1 = unpk(acc[rp][1]);
            float2 t2 = unpk(acc[rp][2]), t3 = unpk(acc[rp][3]);
            const int row = rowbase + 2 * rp;
            float4 v;
            v.x = t0.x + b0; v.y = t1.x + b1; v.z = t2.x + b2; v.w = t3.x + b3;
            *(float4*)(out + ((size_t)(n0 + row) * NRES + r) * CIN + colbase) = v;
            v.x = t0.y + b0; v.y = t1.y + b1; v.z = t2.y + b2; v.w = t3.y + b3;
            *(float4*)(out + ((size_t)(n0 + row + 1) * NRES + r) * CIN + colbase) = v;
        }
    }
}

extern "C" void kernel_launch(void* const* d_in, const int* in_sizes, int n_in,
                              void* d_out, int out_size) {
    const float* m    = (const float*)d_in[0];
    const float* mask = (const float*)d_in[1];
    const float* lnw  = (const float*)d_in[2];
    const float* lnb  = (const float*)d_in[3];
    const float* wq   = (const float*)d_in[4];
    const float* wk   = (const float*)d_in[5];
    const float* wv   = (const float*)d_in[6];
    const float* wg   = (const float*)d_in[7];
    const float* bg   = (const float*)d_in[8];
    const float* wo   = (const float*)d_in[9];
    const float* bo   = (const float*)d_in[10];
    float* out = (float*)d_out;

    cudaFuncSetAttribute(pass1_kernel,
                         cudaFuncAttributeMaxDynamicSharedMemorySize, P1_SMEM_BYTES);
    cudaFuncSetAttribute(pass3_kernel,
                         cudaFuncAttributeMaxDynamicSharedMemorySize, P3_SMEM_BYTES);

    pass1_kernel<<<dim3(NRES, 16), 256, P1_SMEM_BYTES>>>(m, mask, lnw, lnb, wk, wv);
    pass2_kernel<<<NRES, 512>>>(wq);
    pass3_kernel<<<dim3(NRES, 16), 256, P3_SMEM_BYTES>>>(wg, bg, wo, bo, out);
}